// round 10
// baseline (speedup 1.0000x reference)
#include <cuda_runtime.h>

// DenselyCnnAttLayer, warp==CTA==row + L2::256B fetch-granularity hint.
// out[b,s,d] = sum_l softmax_m( sum_l' s[b,s,l'] * Ws[s,l',m] )[l] * x_l[b,s,d]
// where s[b,s,l] = sum_d x_l[b,s,d].  B=64, S=512, L=6, D=512, fp32.
//
// Traffic minimal: 6 reads + 1 write = ~470MB. Champion R9: ncu 66.0us,
// 6.76TB/s (85.4% of spec). R10 adds ld.global.cs.L2::256B on the payload
// loads — dense stream, so 256B L2 fetch granules halve the L2->DRAM request
// count, improving memory-controller scheduling efficiency. Structure
// otherwise identical to R9 (the measured best: finest CTA granularity,
// register payload, shuffle reduction, redundant per-lane softmax).
//
// Experiment log: R1 block+barrier 83.5% | R2 smem-stage 72.5% | R3 warp-row
// 84.7% | R4 persistent 78.7% | R5 TMA ring 77.9% | R6 prefetch 72.6% |
// R7 redux.f32 = not on sm_103 | R8 re-land R3 85.0% | R9 warp==CTA 85.4%.

#define DD    512
#define LL    6
#define CHNK  4            // float4 chunks per lane per layer (512/32/4)
#define NTHR  32           // ONE warp per CTA

__device__ __forceinline__ float4 ldcs_256(const float* p) {
    float4 r;
    asm volatile("ld.global.cs.L2::256B.v4.f32 {%0,%1,%2,%3}, [%4];"
                 : "=f"(r.x), "=f"(r.y), "=f"(r.z), "=f"(r.w)
                 : "l"(p));
    return r;
}

__global__ __launch_bounds__(NTHR)
void dense_att_kernel(const float* __restrict__ x0,
                      const float* __restrict__ x1,
                      const float* __restrict__ x2,
                      const float* __restrict__ x3,
                      const float* __restrict__ x4,
                      const float* __restrict__ x5,
                      const float* __restrict__ Ws,   // [S, L, L]
                      float* __restrict__ out)        // [B, S, D]
{
    const int lane = threadIdx.x;
    const int row  = blockIdx.x;             // b*S + s
    const int s    = row & 511;              // S = 512

    // lane handles float4s at d = c*128 + lane*4, c = 0..3 (coalesced)
    const size_t base = (size_t)row * DD + (size_t)lane * 4;

    const float* xs[LL] = {x0, x1, x2, x3, x4, x5};

    // 24 front-batched streaming LDG.128 with 256B L2 fetch granularity.
    float4 v[LL][CHNK];
#pragma unroll
    for (int j = 0; j < LL; j++) {
#pragma unroll
        for (int c = 0; c < CHNK; c++) {
            v[j][c] = ldcs_256(xs[j] + base + c * 128);
        }
    }

    float p[LL];
#pragma unroll
    for (int j = 0; j < LL; j++) {
        float a0 = (v[j][0].x + v[j][0].y) + (v[j][0].z + v[j][0].w);
        float a1 = (v[j][1].x + v[j][1].y) + (v[j][1].z + v[j][1].w);
        float a2 = (v[j][2].x + v[j][2].y) + (v[j][2].z + v[j][2].w);
        float a3 = (v[j][3].x + v[j][3].y) + (v[j][3].z + v[j][3].w);
        p[j] = (a0 + a1) + (a2 + a3);
    }

    // Warp butterfly: all lanes end with the full per-layer sums.
    // (redux.sync.add is integer-only on sm_103 — shuffle tree required.)
#pragma unroll
    for (int off = 16; off > 0; off >>= 1) {
#pragma unroll
        for (int j = 0; j < LL; j++) {
            p[j] += __shfl_xor_sync(0xffffffffu, p[j], off);
        }
    }

    // Redundant per-lane 6x6 projection + softmax (warp-uniform Ws loads;
    // Ws is 73KB total, L2/L1 hot).
    const float* W = Ws + (size_t)s * (LL * LL);
    float logit[LL];
#pragma unroll
    for (int m = 0; m < LL; m++) logit[m] = 0.0f;
#pragma unroll
    for (int l = 0; l < LL; l++) {
        const float sl = p[l];
#pragma unroll
        for (int m = 0; m < LL; m++) {
            logit[m] = fmaf(sl, __ldg(W + l * LL + m), logit[m]);
        }
    }

    float mx = logit[0];
#pragma unroll
    for (int m = 1; m < LL; m++) mx = fmaxf(mx, logit[m]);
    float a[LL];
    float den = 0.0f;
#pragma unroll
    for (int m = 0; m < LL; m++) {
        a[m] = __expf(logit[m] - mx);
        den += a[m];
    }
    const float inv = __frcp_rn(den);
#pragma unroll
    for (int m = 0; m < LL; m++) a[m] *= inv;

    // Weighted combine over layers, 4 coalesced streaming stores.
#pragma unroll
    for (int c = 0; c < CHNK; c++) {
        float4 o;
        o.x = o.y = o.z = o.w = 0.0f;
#pragma unroll
        for (int j = 0; j < LL; j++) {
            o.x = fmaf(a[j], v[j][c].x, o.x);
            o.y = fmaf(a[j], v[j][c].y, o.y);
            o.z = fmaf(a[j], v[j][c].z, o.z);
            o.w = fmaf(a[j], v[j][c].w, o.w);
        }
        __stcs(reinterpret_cast<float4*>(out + base + c * 128), o);
    }
}

extern "C" void kernel_launch(void* const* d_in, const int* in_sizes, int n_in,
                              void* d_out, int out_size)
{
    const float* x0 = (const float*)d_in[0];
    const float* x1 = (const float*)d_in[1];
    const float* x2 = (const float*)d_in[2];
    const float* x3 = (const float*)d_in[3];
    const float* x4 = (const float*)d_in[4];
    const float* x5 = (const float*)d_in[5];
    const float* Ws = (const float*)d_in[6];
    float* out = (float*)d_out;

    const int rows = in_sizes[0] / DD;          // B*S = 32768
    dense_att_kernel<<<rows, NTHR>>>(x0, x1, x2, x3, x4, x5, Ws, out);
}

// round 11
// speedup vs baseline: 1.0009x; 1.0009x over previous
#include <cuda_runtime.h>

// DenselyCnnAttLayer — FINAL converged kernel (R9 structure, re-landed).
// out[b,s,d] = sum_l softmax_m( sum_l' s[b,s,l'] * Ws[s,l',m] )[l] * x_l[b,s,d]
// where s[b,s,l] = sum_d x_l[b,s,d].  B=64, S=512, L=6, D=512, fp32.
//
// One warp == one CTA == one (b,s) row. 24 front-batched streaming LDG.128
// into registers, shuffle-tree reduction, redundant per-lane 6x6 projection +
// softmax, 4 coalesced streaming STG.128. Grid 32768 x 32 threads.
//
// Why this shape is optimal (full measured matrix, 10 rounds):
//   R1 block-per-row+barrier 83.5% | R2 smem staging 72.5% (L1tex contention)
//   R3 warp-per-row 84.7%          | R4 persistent grid-stride 78.7%
//   R5 TMA 2-slot ring 77.9%       | R6 L2-prefetch double-row 72.6%
//   R7 redux.sync.add.f32: integer-only on sm_103 (build fail)
//   R8 = R3 re-land 85.0%          | R9 warp==CTA 85.4% / ncu 66.0us  <-- best
//   R10 ld...L2::256B hint 83.3% (request-granularity not a B300 lever)
// Traffic is provably minimal: 6 reads + 1 write = ~470MB, and
// 66.0us x 6.76TB/s == 470MB. The kernel sits on the mixed-stream HBM3e
// throughput ceiling (~85% of 8TB/s spec); the HW CTA scheduler rotating
// 32768 minimal CTAs is the best memory-parallelism engine for this stream.

#define DD    512
#define LL    6
#define CHNK  4            // float4 chunks per lane per layer (512/32/4)
#define NTHR  32           // ONE warp per CTA

__global__ __launch_bounds__(NTHR)
void dense_att_kernel(const float* __restrict__ x0,
                      const float* __restrict__ x1,
                      const float* __restrict__ x2,
                      const float* __restrict__ x3,
                      const float* __restrict__ x4,
                      const float* __restrict__ x5,
                      const float* __restrict__ Ws,   // [S, L, L]
                      float* __restrict__ out)        // [B, S, D]
{
    const int lane = threadIdx.x;
    const int row  = blockIdx.x;             // b*S + s
    const int s    = row & 511;              // S = 512

    // lane handles float4s at d = c*128 + lane*4, c = 0..3 (coalesced)
    const size_t base = (size_t)row * DD + (size_t)lane * 4;

    const float* xs[LL] = {x0, x1, x2, x3, x4, x5};

    // 24 front-batched streaming LDG.128 (each element touched exactly once).
    float4 v[LL][CHNK];
#pragma unroll
    for (int j = 0; j < LL; j++) {
#pragma unroll
        for (int c = 0; c < CHNK; c++) {
            v[j][c] = __ldcs(reinterpret_cast<const float4*>(xs[j] + base + c * 128));
        }
    }

    float p[LL];
#pragma unroll
    for (int j = 0; j < LL; j++) {
        float a0 = (v[j][0].x + v[j][0].y) + (v[j][0].z + v[j][0].w);
        float a1 = (v[j][1].x + v[j][1].y) + (v[j][1].z + v[j][1].w);
        float a2 = (v[j][2].x + v[j][2].y) + (v[j][2].z + v[j][2].w);
        float a3 = (v[j][3].x + v[j][3].y) + (v[j][3].z + v[j][3].w);
        p[j] = (a0 + a1) + (a2 + a3);
    }

    // Warp butterfly: all lanes end with the full per-layer sums.
    // (redux.sync.add is integer-only on sm_103 — shuffle tree required.)
#pragma unroll
    for (int off = 16; off > 0; off >>= 1) {
#pragma unroll
        for (int j = 0; j < LL; j++) {
            p[j] += __shfl_xor_sync(0xffffffffu, p[j], off);
        }
    }

    // Redundant per-lane 6x6 projection + softmax (warp-uniform Ws loads;
    // Ws is 73KB total, L2/L1 hot).
    const float* W = Ws + (size_t)s * (LL * LL);
    float logit[LL];
#pragma unroll
    for (int m = 0; m < LL; m++) logit[m] = 0.0f;
#pragma unroll
    for (int l = 0; l < LL; l++) {
        const float sl = p[l];
#pragma unroll
        for (int m = 0; m < LL; m++) {
            logit[m] = fmaf(sl, __ldg(W + l * LL + m), logit[m]);
        }
    }

    float mx = logit[0];
#pragma unroll
    for (int m = 1; m < LL; m++) mx = fmaxf(mx, logit[m]);
    float a[LL];
    float den = 0.0f;
#pragma unroll
    for (int m = 0; m < LL; m++) {
        a[m] = __expf(logit[m] - mx);
        den += a[m];
    }
    const float inv = __frcp_rn(den);
#pragma unroll
    for (int m = 0; m < LL; m++) a[m] *= inv;

    // Weighted combine over layers, 4 coalesced streaming stores.
#pragma unroll
    for (int c = 0; c < CHNK; c++) {
        float4 o;
        o.x = o.y = o.z = o.w = 0.0f;
#pragma unroll
        for (int j = 0; j < LL; j++) {
            o.x = fmaf(a[j], v[j][c].x, o.x);
            o.y = fmaf(a[j], v[j][c].y, o.y);
            o.z = fmaf(a[j], v[j][c].z, o.z);
            o.w = fmaf(a[j], v[j][c].w, o.w);
        }
        __stcs(reinterpret_cast<float4*>(out + base + c * 128), o);
    }
}

extern "C" void kernel_launch(void* const* d_in, const int* in_sizes, int n_in,
                              void* d_out, int out_size)
{
    const float* x0 = (const float*)d_in[0];
    const float* x1 = (const float*)d_in[1];
    const float* x2 = (const float*)d_in[2];
    const float* x3 = (const float*)d_in[3];
    const float* x4 = (const float*)d_in[4];
    const float* x5 = (const float*)d_in[5];
    const float* Ws = (const float*)d_in[6];
    float* out = (float*)d_out;

    const int rows = in_sizes[0] / DD;          // B*S = 32768
    dense_att_kernel<<<rows, NTHR>>>(x0, x1, x2, x3, x4, x5, Ws, out);
}

// round 12
// speedup vs baseline: 1.0050x; 1.0041x over previous
#include <cuda_runtime.h>

// DenselyCnnAttLayer — converged kernel (R9 structure), final micro-variant.
// out[b,s,d] = sum_l softmax_m( sum_l' s[b,s,l'] * Ws[s,l',m] )[l] * x_l[b,s,d]
// where s[b,s,l] = sum_d x_l[b,s,d].  B=64, S=512, L=6, D=512, fp32.
//
// One warp == one CTA == one (b,s) row. 24 front-batched streaming LDG.128
// into registers, shuffle-tree reduction, redundant per-lane 6x6 projection +
// softmax, 4 coalesced streaming STG.128. Grid 32768 x 32 threads.
//
// R12 micro-tweak vs R9: loads issue c-outer/j-inner so the warp's first 6
// requests target the 6 widely-separated input buffers (6 distinct L2
// slices/DRAM channels) instead of 4 chunks of one buffer. Zero-cost reorder.
//
// Measured matrix (11 rounds): R1 block+barrier 83.5% | R2 smem-stage 72.5% |
// R3 warp-row 84.7% | R4 persistent 78.7% | R5 TMA ring 77.9% | R6 prefetch
// 72.6% | R7 redux.f32 absent on sm_103 | R8 85.0% | R9 warp==CTA 85.4%
// (ncu 66.0us, BEST) | R10 L2::256B 83.3% | R11 R9-reland 84.4% (noise).
// Traffic provably minimal (470MB); kernel sits on the mixed-stream HBM3e
// ceiling (~85% of 8TB/s). This is the converged final answer.

#define DD    512
#define LL    6
#define CHNK  4            // float4 chunks per lane per layer (512/32/4)
#define NTHR  32           // ONE warp per CTA

__global__ __launch_bounds__(NTHR)
void dense_att_kernel(const float* __restrict__ x0,
                      const float* __restrict__ x1,
                      const float* __restrict__ x2,
                      const float* __restrict__ x3,
                      const float* __restrict__ x4,
                      const float* __restrict__ x5,
                      const float* __restrict__ Ws,   // [S, L, L]
                      float* __restrict__ out)        // [B, S, D]
{
    const int lane = threadIdx.x;
    const int row  = blockIdx.x;             // b*S + s
    const int s    = row & 511;              // S = 512

    // lane handles float4s at d = c*128 + lane*4, c = 0..3 (coalesced)
    const size_t base = (size_t)row * DD + (size_t)lane * 4;

    const float* xs[LL] = {x0, x1, x2, x3, x4, x5};

    // 24 front-batched streaming LDG.128, c-outer/j-inner issue order:
    // the first 6 requests hit the 6 distinct input buffers.
    float4 v[LL][CHNK];
#pragma unroll
    for (int c = 0; c < CHNK; c++) {
#pragma unroll
        for (int j = 0; j < LL; j++) {
            v[j][c] = __ldcs(reinterpret_cast<const float4*>(xs[j] + base + c * 128));
        }
    }

    float p[LL];
#pragma unroll
    for (int j = 0; j < LL; j++) {
        float a0 = (v[j][0].x + v[j][0].y) + (v[j][0].z + v[j][0].w);
        float a1 = (v[j][1].x + v[j][1].y) + (v[j][1].z + v[j][1].w);
        float a2 = (v[j][2].x + v[j][2].y) + (v[j][2].z + v[j][2].w);
        float a3 = (v[j][3].x + v[j][3].y) + (v[j][3].z + v[j][3].w);
        p[j] = (a0 + a1) + (a2 + a3);
    }

    // Warp butterfly: all lanes end with the full per-layer sums.
    // (redux.sync.add is integer-only on sm_103 — shuffle tree required.)
#pragma unroll
    for (int off = 16; off > 0; off >>= 1) {
#pragma unroll
        for (int j = 0; j < LL; j++) {
            p[j] += __shfl_xor_sync(0xffffffffu, p[j], off);
        }
    }

    // Redundant per-lane 6x6 projection + softmax (warp-uniform Ws loads;
    // Ws is 73KB total, L2/L1 hot).
    const float* W = Ws + (size_t)s * (LL * LL);
    float logit[LL];
#pragma unroll
    for (int m = 0; m < LL; m++) logit[m] = 0.0f;
#pragma unroll
    for (int l = 0; l < LL; l++) {
        const float sl = p[l];
#pragma unroll
        for (int m = 0; m < LL; m++) {
            logit[m] = fmaf(sl, __ldg(W + l * LL + m), logit[m]);
        }
    }

    float mx = logit[0];
#pragma unroll
    for (int m = 1; m < LL; m++) mx = fmaxf(mx, logit[m]);
    float a[LL];
    float den = 0.0f;
#pragma unroll
    for (int m = 0; m < LL; m++) {
        a[m] = __expf(logit[m] - mx);
        den += a[m];
    }
    const float inv = __frcp_rn(den);
#pragma unroll
    for (int m = 0; m < LL; m++) a[m] *= inv;

    // Weighted combine over layers, 4 coalesced streaming stores.
#pragma unroll
    for (int c = 0; c < CHNK; c++) {
        float4 o;
        o.x = o.y = o.z = o.w = 0.0f;
#pragma unroll
        for (int j = 0; j < LL; j++) {
            o.x = fmaf(a[j], v[j][c].x, o.x);
            o.y = fmaf(a[j], v[j][c].y, o.y);
            o.z = fmaf(a[j], v[j][c].z, o.z);
            o.w = fmaf(a[j], v[j][c].w, o.w);
        }
        __stcs(reinterpret_cast<float4*>(out + base + c * 128), o);
    }
}

extern "C" void kernel_launch(void* const* d_in, const int* in_sizes, int n_in,
                              void* d_out, int out_size)
{
    const float* x0 = (const float*)d_in[0];
    const float* x1 = (const float*)d_in[1];
    const float* x2 = (const float*)d_in[2];
    const float* x3 = (const float*)d_in[3];
    const float* x4 = (const float*)d_in[4];
    const float* x5 = (const float*)d_in[5];
    const float* Ws = (const float*)d_in[6];
    float* out = (float*)d_out;

    const int rows = in_sizes[0] / DD;          // B*S = 32768
    dense_att_kernel<<<rows, NTHR>>>(x0, x1, x2, x3, x4, x5, Ws, out);
}